// round 5
// baseline (speedup 1.0000x reference)
#include <cuda_runtime.h>

// Integer-exact fused QAT conv stack (bit-exact vs fp32 reference).
// All-register: each thread computes 8 output positions end-to-end.
// Weights copied to registers per phase; streaming cache hints on x/z.

#define NT 256   // threads per block
#define PP 8     // output positions per thread

__device__ __forceinline__ int cvtrd(float v) {
    return __float2int_rd(fmaf(v, 128.0f, 0.5f));   // floor(v*128 + 0.5)
}
__device__ __forceinline__ int packsat2(int a, int b, int c) {
    int d;
    asm("cvt.pack.sat.s8.s32.b32 %0, %1, %2, %3;"
        : "=r"(d) : "r"(a), "r"(b), "r"(c));
    return d;
}
// bytes [v0,v1,v2,v3]; same helper for weights and data -> dp4a order-invariant
__device__ __forceinline__ int pack4sat(int v0, int v1, int v2, int v3) {
    return packsat2(v1, v0, packsat2(v3, v2, 0));
}
__device__ __forceinline__ int qpack(float a, float b, float c, float d) {
    return pack4sat(cvtrd(a), cvtrd(b), cvtrd(c), cvtrd(d));
}

// wall layout: [0..23] w1 packed (oc*3+k), [24..31] 128*b1+64,
//              [32..43] w2 packed (oc*6+k*2+h), [44..45] 128*b2+64
template <bool GUARD>
__device__ __forceinline__ void tail_compute(
    const int* xw, const int* wall, int base, int L, float* ob)
{
    // ---- stage 2: weights in registers ----
    int w1r[24], bo1r[8];
#pragma unroll
    for (int i = 0; i < 24; i++) w1r[i] = wall[i];
#pragma unroll
    for (int i = 0; i < 8; i++)  bo1r[i] = wall[24 + i];

    int yl[PP + 2], yh[PP + 2];
#pragma unroll
    for (int i = 0; i < PP + 2; i++) {
        int x0 = xw[i], x1 = xw[i + 1], x2 = xw[i + 2];
        int yv[8];
#pragma unroll
        for (int oc = 0; oc < 8; oc++) {
            int acc = __dp4a(x0, w1r[oc * 3 + 0], bo1r[oc]);
            acc     = __dp4a(x1, w1r[oc * 3 + 1], acc);
            acc     = __dp4a(x2, w1r[oc * 3 + 2], acc);
            yv[oc]  = acc >> 7;
        }
        int lo = pack4sat(yv[0], yv[1], yv[2], yv[3]);
        int hi = pack4sat(yv[4], yv[5], yv[6], yv[7]);
        if (GUARD) {
            int q = base - 1 + i;
            bool valid = (q >= 0) && (q < L);
            lo = valid ? lo : 0;
            hi = valid ? hi : 0;
        }
        yl[i] = lo; yh[i] = hi;
    }

    // ---- stage 3: weights in registers ----
    int w2r[12], bo2r[2];
#pragma unroll
    for (int i = 0; i < 12; i++) w2r[i] = wall[32 + i];
    bo2r[0] = wall[44]; bo2r[1] = wall[45];

    float f0[PP], f1[PP];
#pragma unroll
    for (int p = 0; p < PP; p++) {
        int a0 = __dp4a(yl[p],     w2r[0], bo2r[0]);
        a0     = __dp4a(yh[p],     w2r[1], a0);
        a0     = __dp4a(yl[p + 1], w2r[2], a0);
        a0     = __dp4a(yh[p + 1], w2r[3], a0);
        a0     = __dp4a(yl[p + 2], w2r[4], a0);
        a0     = __dp4a(yh[p + 2], w2r[5], a0);
        int a1 = __dp4a(yl[p],     w2r[6], bo2r[1]);
        a1     = __dp4a(yh[p],     w2r[7], a1);
        a1     = __dp4a(yl[p + 1], w2r[8], a1);
        a1     = __dp4a(yh[p + 1], w2r[9], a1);
        a1     = __dp4a(yl[p + 2], w2r[10], a1);
        a1     = __dp4a(yh[p + 2], w2r[11], a1);
        f0[p] = (float)min(max(a0 >> 7, -128), 127) * 0.0078125f;
        f1[p] = (float)min(max(a1 >> 7, -128), 127) * 0.0078125f;
    }
    __stcs((float4*)(ob + base),     make_float4(f0[0], f0[1], f0[2], f0[3]));
    __stcs((float4*)(ob + base + 4), make_float4(f0[4], f0[5], f0[6], f0[7]));
    __stcs((float4*)(ob + (size_t)L + base),
           make_float4(f1[0], f1[1], f1[2], f1[3]));
    __stcs((float4*)(ob + (size_t)L + base + 4),
           make_float4(f1[4], f1[5], f1[6], f1[7]));
}

__global__ __launch_bounds__(NT, 3) void fused_qconv_reg2(
    const float* __restrict__ x,
    const float* __restrict__ w1, const float* __restrict__ b1,
    const float* __restrict__ gamma, const float* __restrict__ beta,
    const float* __restrict__ bn_mean, const float* __restrict__ bn_var,
    const float* __restrict__ w2, const float* __restrict__ b2,
    float* __restrict__ out, int L)
{
    __shared__ int wall[48];
    const int tid = threadIdx.x;

    // ---- weight prep (tiny, once per block) ----
    if (tid < 24) {
        int oc = tid / 3, k = tid % 3;
        float sf = (float)((double)gamma[oc] / sqrt((double)bn_var[oc] + 1e-5));
        const float* wb = w1 + oc * 12 + k;
        wall[tid] = qpack(wb[0] * sf, wb[3] * sf, wb[6] * sf, wb[9] * sf);
    } else if (tid < 32) {
        int oc = tid - 24;
        float sf = (float)((double)gamma[oc] / sqrt((double)bn_var[oc] + 1e-5));
        int bi = min(max(cvtrd((b1[oc] - bn_mean[oc]) * sf + beta[oc]), -128), 127);
        wall[tid] = bi * 128 + 64;
    } else if (tid < 44) {
        int t = tid - 32, oc = t / 6, r = t % 6, k = r >> 1, h = r & 1;
        const float* wb = w2 + oc * 24 + h * 12 + k;
        wall[tid] = qpack(wb[0], wb[3], wb[6], wb[9]);
    } else if (tid < 46) {
        wall[tid] = min(max(cvtrd(b2[tid - 44]), -128), 127) * 128 + 64;
    }
    __syncthreads();

    const int bb   = blockIdx.y;
    const int base = (blockIdx.x * NT + tid) * PP;   // first z position
    const float* xb = x + (size_t)bb * 4 * L;
    float* ob = out + (size_t)bb * 2 * L;

    int xw[12];   // packed fq(x), xw[j] = position base-2+j

    if (base >= 4 && base + 12 <= L) {
        const float* p0 = xb + (base - 4);
        const float* p1 = p0 + (size_t)L;
        const float* p2 = p0 + (size_t)2 * L;
        const float* p3 = p0 + (size_t)3 * L;

        float4 a0 = __ldcs((const float4*)(p0 +  0));
        float4 a1 = __ldcs((const float4*)(p0 +  4));
        float4 a2 = __ldcs((const float4*)(p0 +  8));
        float4 a3 = __ldcs((const float4*)(p0 + 12));
        float4 b0 = __ldcs((const float4*)(p1 +  0));
        float4 b1v = __ldcs((const float4*)(p1 +  4));
        float4 b2v = __ldcs((const float4*)(p1 +  8));
        float4 b3 = __ldcs((const float4*)(p1 + 12));
        float4 c0 = __ldcs((const float4*)(p2 +  0));
        float4 c1 = __ldcs((const float4*)(p2 +  4));
        float4 c2 = __ldcs((const float4*)(p2 +  8));
        float4 c3 = __ldcs((const float4*)(p2 + 12));
        float4 d0 = __ldcs((const float4*)(p3 +  0));
        float4 d1 = __ldcs((const float4*)(p3 +  4));
        float4 d2 = __ldcs((const float4*)(p3 +  8));
        float4 d3 = __ldcs((const float4*)(p3 + 12));

        xw[0]  = qpack(a0.z, b0.z,  c0.z, d0.z);
        xw[1]  = qpack(a0.w, b0.w,  c0.w, d0.w);
        xw[2]  = qpack(a1.x, b1v.x, c1.x, d1.x);
        xw[3]  = qpack(a1.y, b1v.y, c1.y, d1.y);
        xw[4]  = qpack(a1.z, b1v.z, c1.z, d1.z);
        xw[5]  = qpack(a1.w, b1v.w, c1.w, d1.w);
        xw[6]  = qpack(a2.x, b2v.x, c2.x, d2.x);
        xw[7]  = qpack(a2.y, b2v.y, c2.y, d2.y);
        xw[8]  = qpack(a2.z, b2v.z, c2.z, d2.z);
        xw[9]  = qpack(a2.w, b2v.w, c2.w, d2.w);
        xw[10] = qpack(a3.x, b3.x,  c3.x, d3.x);
        xw[11] = qpack(a3.y, b3.y,  c3.y, d3.y);

        tail_compute<false>(xw, wall, base, L, ob);
    } else {
        // ---- slow path: batch-row edges only ----
#pragma unroll
        for (int j = 0; j < 12; j++) {
            int p = base - 2 + j, w = 0;
            if (p >= 0 && p < L)
                w = qpack(xb[p], xb[(size_t)L + p],
                          xb[(size_t)2 * L + p], xb[(size_t)3 * L + p]);
            xw[j] = w;
        }
        tail_compute<true>(xw, wall, base, L, ob);
    }
}

extern "C" void kernel_launch(void* const* d_in, const int* in_sizes, int n_in,
                              void* d_out, int out_size)
{
    const float* x       = (const float*)d_in[0];
    const float* w1      = (const float*)d_in[1];
    const float* b1      = (const float*)d_in[2];
    const float* gamma   = (const float*)d_in[3];
    const float* beta    = (const float*)d_in[4];
    const float* bn_mean = (const float*)d_in[5];
    const float* bn_var  = (const float*)d_in[6];
    const float* w2      = (const float*)d_in[7];
    const float* b2      = (const float*)d_in[8];
    float* out = (float*)d_out;

    const int B = 16;
    const int L = in_sizes[0] / (B * 4);

    dim3 grid(L / (NT * PP), B);
    fused_qconv_reg2<<<grid, NT>>>(
        x, w1, b1, gamma, beta, bn_mean, bn_var, w2, b2, out, L);
}